// round 1
// baseline (speedup 1.0000x reference)
#include <cuda_runtime.h>
#include <math.h>
#include <stdint.h>

#define B_  2
#define L_  2048
#define D_  1024
#define H_  16
#define DH_ 64
#define M_  (B_*L_)   // 4096

// ---------------- scratch (static device globals; no runtime allocation) ----
__device__ float g_P[4][(size_t)M_*D_];   // raw projections q,k,v,u  (64 MB)
__device__ float g_Qh[(size_t)M_*D_];     // [B,H,L,DH], pre-scaled by DH^-0.5
__device__ float g_Kh[(size_t)M_*D_];
__device__ float g_Vh[(size_t)M_*D_];     // gated V
__device__ float g_Oh[(size_t)M_*D_];     // attention output [B,H,L,DH]
__device__ float g_cos[L_*32];
__device__ float g_sin[L_*32];

// ---------------- RoPE table (double precision, tiny) -----------------------
__global__ void rope_table_kernel() {
    int idx = blockIdx.x * blockDim.x + threadIdx.x;
    if (idx >= L_ * 32) return;
    int l = idx >> 5, j = idx & 31;
    double invf = exp(-((double)(2 * j) / 64.0) * log(10000.0));
    double a = (double)l * invf;
    g_cos[idx] = (float)cos(a);
    g_sin[idx] = (float)sin(a);
}

// ---------------- fused projection GEMM: P[w] = X_w @ W_w + b_w -------------
// grid.x: 64 tiles (4 weights x 16 n-tiles of 64), grid.y: 32 m-tiles of 128
__global__ __launch_bounds__(256) void proj_gemm_kernel(
    const float* __restrict__ Aq, const float* __restrict__ Ak, const float* __restrict__ Av,
    const float* __restrict__ Wq, const float* __restrict__ bq,
    const float* __restrict__ Wk, const float* __restrict__ bk,
    const float* __restrict__ Wv, const float* __restrict__ bv,
    const float* __restrict__ Wu, const float* __restrict__ bu)
{
    __shared__ float As[16][129];
    __shared__ float Bs[16][64];

    int wsel = blockIdx.x >> 4;
    int n0 = (blockIdx.x & 15) * 64;
    int m0 = blockIdx.y * 128;

    const float* A    = (wsel == 1) ? Ak : (wsel == 2) ? Av : Aq;   // U uses query
    const float* W    = (wsel == 0) ? Wq : (wsel == 1) ? Wk : (wsel == 2) ? Wv : Wu;
    const float* bias = (wsel == 0) ? bq : (wsel == 1) ? bk : (wsel == 2) ? bv : bu;
    float* out = g_P[wsel];

    int ty = threadIdx.x >> 4, tx = threadIdx.x & 15;
    float acc[8][4];
#pragma unroll
    for (int i = 0; i < 8; i++)
#pragma unroll
        for (int j = 0; j < 4; j++) acc[i][j] = 0.f;

    for (int kt = 0; kt < D_; kt += 16) {
#pragma unroll
        for (int u = 0; u < 2; u++) {
            int lid = threadIdx.x * 2 + u;           // 0..511
            int r = lid >> 2, cseg = lid & 3;
            float4 v = *reinterpret_cast<const float4*>(&A[(size_t)(m0 + r) * D_ + kt + cseg * 4]);
            As[cseg * 4 + 0][r] = v.x; As[cseg * 4 + 1][r] = v.y;
            As[cseg * 4 + 2][r] = v.z; As[cseg * 4 + 3][r] = v.w;
        }
        {
            int r = threadIdx.x >> 4, cseg = threadIdx.x & 15;
            float4 v = *reinterpret_cast<const float4*>(&W[(size_t)(kt + r) * D_ + n0 + cseg * 4]);
            *reinterpret_cast<float4*>(&Bs[r][cseg * 4]) = v;
        }
        __syncthreads();
#pragma unroll
        for (int k = 0; k < 16; k++) {
            float a[8], bb[4];
#pragma unroll
            for (int i = 0; i < 8; i++) a[i] = As[k][ty * 8 + i];
#pragma unroll
            for (int j = 0; j < 4; j++) bb[j] = Bs[k][tx * 4 + j];
#pragma unroll
            for (int i = 0; i < 8; i++)
#pragma unroll
                for (int j = 0; j < 4; j++) acc[i][j] = fmaf(a[i], bb[j], acc[i][j]);
        }
        __syncthreads();
    }
#pragma unroll
    for (int i = 0; i < 8; i++) {
        int m = m0 + ty * 8 + i;
#pragma unroll
        for (int j = 0; j < 4; j++)
            out[(size_t)m * D_ + n0 + tx * 4 + j] = acc[i][j] + bias[n0 + tx * 4 + j];
    }
}

// ---------------- elementwise prep: RoPE, gating, head layout ---------------
__global__ __launch_bounds__(256) void prep_kernel(
    const int* __restrict__ action_ids,
    const float* __restrict__ action_emb,
    const float* __restrict__ Wap,
    const float* __restrict__ bap)
{
    int idx = blockIdx.x * blockDim.x + threadIdx.x;
    if (idx >= M_ * D_) return;
    int m = idx / D_, d = idx % D_;
    int b = m / L_, l = m % L_;
    int h = d >> 6, dh = d & 63;

    float q  = g_P[0][(size_t)idx];
    float kk = g_P[1][(size_t)idx];
    float v  = g_P[2][(size_t)idx];
    float u  = g_P[3][(size_t)idx];

    int aid = action_ids[m];
    float g = bap[d];
    const float* ae = action_emb + aid * 16;
#pragma unroll
    for (int j = 0; j < 16; j++) g = fmaf(ae[j], Wap[j * D_ + d], g);
    float gate = 1.f / (1.f + __expf(-(u + g)));

    int partner = (dh < 32) ? (dh + 32) : (dh - 32);
    float sgn = (dh < 32) ? -1.f : 1.f;
    size_t pidx = (size_t)m * D_ + h * 64 + partner;
    float qr = sgn * g_P[0][pidx];
    float kr = sgn * g_P[1][pidx];

    int ji = dh >> 1;
    float c = g_cos[l * 32 + ji], s = g_sin[l * 32 + ji];

    size_t oidx = ((size_t)(b * H_ + h) * L_ + l) * DH_ + dh;
    g_Qh[oidx] = (q * c + qr * s) * 0.125f;   // pre-scale by DH^-0.5
    g_Kh[oidx] = kk * c + kr * s;
    g_Vh[oidx] = v * gate;
}

// ---------------- flash attention (fp32, online softmax) -------------------
// grid: (L/64 query tiles, B*H); 256 threads; dynamic smem ~70KB
__global__ __launch_bounds__(256) void attn_kernel(
    const unsigned char* __restrict__ maskb,
    const int* __restrict__ td,
    const float* __restrict__ td_emb,
    const float* __restrict__ td_gate)
{
    extern __shared__ float sm[];
    float* Qs = sm;                    // [64][65]
    float* Ks = sm + 64 * 65;          // [64][65]
    float* Vs = sm + 2 * 64 * 65;      // [64][65]
    float* Ps = sm + 3 * 64 * 65;      // [64][65]
    float* biask = sm + 4 * 64 * 65;   // [64]
    unsigned char* Ms = (unsigned char*)(biask + 64); // [64][64]

    int tid = threadIdx.x;
    int tys = tid >> 4, txs = tid & 15;
    int q0 = blockIdx.x * 64;
    int bh = blockIdx.y;
    int b = bh >> 4, h = bh & 15;

    const float* Qbase = g_Qh + ((size_t)bh * L_) * DH_;
    const float* Kbase = g_Kh + ((size_t)bh * L_) * DH_;
    const float* Vbase = g_Vh + ((size_t)bh * L_) * DH_;

#pragma unroll
    for (int i = 0; i < 4; i++) {
        int fid = tid + i * 256;
        int r = fid >> 4, c4 = (fid & 15) * 4;
        float4 v = *(const float4*)&Qbase[(size_t)(q0 + r) * DH_ + c4];
        float* dst = &Qs[r * 65 + c4];
        dst[0] = v.x; dst[1] = v.y; dst[2] = v.z; dst[3] = v.w;
    }

    // mask element width sniff: bool(1B) stores give nonzero byte 1; int32/float give 0
    int mwid = (maskb[0] != 0 && maskb[1] != 0) ? 1 : 4;
    float sg = 1.f / (1.f + __expf(-td_gate[0]));

    float o[4][4], m_run[4], l_run[4];
#pragma unroll
    for (int i = 0; i < 4; i++) {
        m_run[i] = -INFINITY; l_run[i] = 0.f;
#pragma unroll
        for (int j = 0; j < 4; j++) o[i][j] = 0.f;
    }

    for (int t = 0; t < L_ / 64; t++) {
        int k0 = t * 64;
        __syncthreads();  // previous tile's Ps/Ks/Vs fully consumed
#pragma unroll
        for (int i = 0; i < 4; i++) {
            int fid = tid + i * 256;
            int r = fid >> 4, c4 = (fid & 15) * 4;
            float4 kv = *(const float4*)&Kbase[(size_t)(k0 + r) * DH_ + c4];
            float* dk = &Ks[r * 65 + c4];
            dk[0] = kv.x; dk[1] = kv.y; dk[2] = kv.z; dk[3] = kv.w;
            float4 vv = *(const float4*)&Vbase[(size_t)(k0 + r) * DH_ + c4];
            float* dv = &Vs[r * 65 + c4];
            dv[0] = vv.x; dv[1] = vv.y; dv[2] = vv.z; dv[3] = vv.w;
        }
        if (tid < 64) {
            int tv = td[b * L_ + k0 + tid];
            tv = min(max(tv, 0), 127);
            biask[tid] = sg * td_emb[tv * H_ + h];
        }
        if (mwid == 1) {
#pragma unroll
            for (int i = 0; i < 16; i++) {
                int idx = tid + i * 256;
                int qq = idx >> 6, kk2 = idx & 63;
                Ms[idx] = maskb[(size_t)(b * L_ + q0 + qq) * L_ + k0 + kk2];
            }
        } else {
            const unsigned int* m32 = (const unsigned int*)maskb;
#pragma unroll
            for (int i = 0; i < 16; i++) {
                int idx = tid + i * 256;
                int qq = idx >> 6, kk2 = idx & 63;
                Ms[idx] = (m32[(size_t)(b * L_ + q0 + qq) * L_ + k0 + kk2] != 0u) ? 1 : 0;
            }
        }
        __syncthreads();

        // scores S = Qs . Ks^T  (Q pre-scaled)
        float s[4][4];
#pragma unroll
        for (int i = 0; i < 4; i++)
#pragma unroll
            for (int j = 0; j < 4; j++) s[i][j] = 0.f;
#pragma unroll 8
        for (int dh = 0; dh < 64; dh++) {
            float a[4], bb[4];
#pragma unroll
            for (int i = 0; i < 4; i++) a[i] = Qs[(tys * 4 + i) * 65 + dh];
#pragma unroll
            for (int j = 0; j < 4; j++) bb[j] = Ks[(txs * 4 + j) * 65 + dh];
#pragma unroll
            for (int i = 0; i < 4; i++)
#pragma unroll
                for (int j = 0; j < 4; j++) s[i][j] = fmaf(a[i], bb[j], s[i][j]);
        }
#pragma unroll
        for (int i = 0; i < 4; i++)
#pragma unroll
            for (int j = 0; j < 4; j++) {
                int kc = txs * 4 + j;
                float v2 = s[i][j] + biask[kc];
                s[i][j] = Ms[(tys * 4 + i) * 64 + kc] ? v2 : -INFINITY;
            }

        // online softmax update
#pragma unroll
        for (int i = 0; i < 4; i++) {
            float mt = fmaxf(fmaxf(s[i][0], s[i][1]), fmaxf(s[i][2], s[i][3]));
#pragma unroll
            for (int off = 8; off >= 1; off >>= 1)
                mt = fmaxf(mt, __shfl_xor_sync(0xffffffffu, mt, off));
            float mn = fmaxf(m_run[i], mt);
            float sc = (m_run[i] == -INFINITY) ? 0.f : __expf(m_run[i] - mn);
            float mnu = (mn == -INFINITY) ? 0.f : mn;
            float p0 = __expf(s[i][0] - mnu);
            float p1 = __expf(s[i][1] - mnu);
            float p2 = __expf(s[i][2] - mnu);
            float p3 = __expf(s[i][3] - mnu);
            float ls = (p0 + p1) + (p2 + p3);
#pragma unroll
            for (int off = 8; off >= 1; off >>= 1)
                ls += __shfl_xor_sync(0xffffffffu, ls, off);
            l_run[i] = l_run[i] * sc + ls;
            m_run[i] = mn;
            float* pr = &Ps[(tys * 4 + i) * 65 + txs * 4];
            pr[0] = p0; pr[1] = p1; pr[2] = p2; pr[3] = p3;
#pragma unroll
            for (int j = 0; j < 4; j++) o[i][j] *= sc;
        }
        __syncthreads();

        // o += Ps @ Vs
#pragma unroll 4
        for (int c = 0; c < 64; c++) {
            float a[4], vv[4];
#pragma unroll
            for (int i = 0; i < 4; i++) a[i] = Ps[(tys * 4 + i) * 65 + c];
#pragma unroll
            for (int j = 0; j < 4; j++) vv[j] = Vs[c * 65 + txs * 4 + j];
#pragma unroll
            for (int i = 0; i < 4; i++)
#pragma unroll
                for (int j = 0; j < 4; j++) o[i][j] = fmaf(a[i], vv[j], o[i][j]);
        }
    }

#pragma unroll
    for (int i = 0; i < 4; i++) {
        float inv = 1.f / l_run[i];
#pragma unroll
        for (int j = 0; j < 4; j++)
            g_Oh[((size_t)bh * L_ + q0 + tys * 4 + i) * DH_ + txs * 4 + j] = o[i][j] * inv;
    }
}

// ---------------- output GEMM: out = Oh(flat) @ Wo + bo ---------------------
__global__ __launch_bounds__(256) void out_gemm_kernel(
    const float* __restrict__ Wo, const float* __restrict__ bo, float* __restrict__ out)
{
    __shared__ float As[16][129];
    __shared__ float Bs[16][64];

    int n0 = blockIdx.x * 64;
    int m0 = blockIdx.y * 128;
    int ty = threadIdx.x >> 4, tx = threadIdx.x & 15;

    float acc[8][4];
#pragma unroll
    for (int i = 0; i < 8; i++)
#pragma unroll
        for (int j = 0; j < 4; j++) acc[i][j] = 0.f;

    for (int kt = 0; kt < D_; kt += 16) {
#pragma unroll
        for (int u = 0; u < 2; u++) {
            int lid = threadIdx.x * 2 + u;
            int r = lid >> 2, cseg = lid & 3;
            int m = m0 + r;
            int bI = m >> 11, lI = m & 2047;
            int k = kt + cseg * 4;
            int hI = k >> 6, dhI = k & 63;
            float4 v = *(const float4*)&g_Oh[(((size_t)bI * H_ + hI) * L_ + lI) * DH_ + dhI];
            As[cseg * 4 + 0][r] = v.x; As[cseg * 4 + 1][r] = v.y;
            As[cseg * 4 + 2][r] = v.z; As[cseg * 4 + 3][r] = v.w;
        }
        {
            int r = threadIdx.x >> 4, cseg = threadIdx.x & 15;
            float4 v = *(const float4*)&Wo[(size_t)(kt + r) * D_ + n0 + cseg * 4];
            *reinterpret_cast<float4*>(&Bs[r][cseg * 4]) = v;
        }
        __syncthreads();
#pragma unroll
        for (int k = 0; k < 16; k++) {
            float a[8], bb[4];
#pragma unroll
            for (int i = 0; i < 8; i++) a[i] = As[k][ty * 8 + i];
#pragma unroll
            for (int j = 0; j < 4; j++) bb[j] = Bs[k][tx * 4 + j];
#pragma unroll
            for (int i = 0; i < 8; i++)
#pragma unroll
                for (int j = 0; j < 4; j++) acc[i][j] = fmaf(a[i], bb[j], acc[i][j]);
        }
        __syncthreads();
    }
#pragma unroll
    for (int i = 0; i < 8; i++) {
        int m = m0 + ty * 8 + i;
#pragma unroll
        for (int j = 0; j < 4; j++)
            out[(size_t)m * D_ + n0 + tx * 4 + j] = acc[i][j] + bo[n0 + tx * 4 + j];
    }
}

// ---------------- launch ----------------------------------------------------
extern "C" void kernel_launch(void* const* d_in, const int* in_sizes, int n_in,
                              void* d_out, int out_size)
{
    const float* query      = (const float*)d_in[0];
    const float* key        = (const float*)d_in[1];
    const float* value      = (const float*)d_in[2];
    const unsigned char* am = (const unsigned char*)d_in[3];
    const int*   action_ids = (const int*)d_in[4];
    const int*   time_delta = (const int*)d_in[5];
    const float* Wq = (const float*)d_in[6];
    const float* bq = (const float*)d_in[7];
    const float* Wk = (const float*)d_in[8];
    const float* bk = (const float*)d_in[9];
    const float* Wv = (const float*)d_in[10];
    const float* bv = (const float*)d_in[11];
    const float* Wu = (const float*)d_in[12];
    const float* bu = (const float*)d_in[13];
    const float* Wo = (const float*)d_in[14];
    const float* bo = (const float*)d_in[15];
    const float* action_emb = (const float*)d_in[16];
    const float* Wap = (const float*)d_in[17];
    const float* bap = (const float*)d_in[18];
    const float* td_emb  = (const float*)d_in[19];
    const float* td_gate = (const float*)d_in[20];
    float* out = (float*)d_out;

    rope_table_kernel<<<(L_ * 32 + 255) / 256, 256>>>();

    proj_gemm_kernel<<<dim3(64, 32), 256>>>(query, key, value,
                                            Wq, bq, Wk, bk, Wv, bv, Wu, bu);

    prep_kernel<<<(M_ * D_ + 255) / 256, 256>>>(action_ids, action_emb, Wap, bap);

    const int attn_smem = (4 * 64 * 65 + 64) * (int)sizeof(float) + 64 * 64;
    cudaFuncSetAttribute(attn_kernel, cudaFuncAttributeMaxDynamicSharedMemorySize, attn_smem);
    attn_kernel<<<dim3(L_ / 64, B_ * H_), 256, attn_smem>>>(am, time_delta, td_emb, td_gate);

    out_gemm_kernel<<<dim3(D_ / 64, M_ / 128), 256>>>(Wo, bo, out);
}

// round 2
// speedup vs baseline: 1.3548x; 1.3548x over previous
#include <cuda_runtime.h>
#include <math.h>
#include <stdint.h>

#define B_  2
#define L_  2048
#define D_  1024
#define H_  16
#define DH_ 64
#define M_  (B_*L_)   // 4096

// ---------------- scratch (static device globals; no runtime allocation) ----
__device__ float g_P[4][(size_t)M_*D_];   // raw projections q,k,v,u
__device__ float g_Qh[(size_t)M_*D_];     // [B,H,L,DH], pre-scaled by DH^-0.5
__device__ float g_Kh[(size_t)M_*D_];
__device__ float g_Vh[(size_t)M_*D_];     // gated V
__device__ float g_Oh[(size_t)M_*D_];     // attention output [B,H,L,DH]
__device__ float g_cos[L_*32];
__device__ float g_sin[L_*32];

// ---------------- helpers ---------------------------------------------------
__device__ __forceinline__ unsigned f2tf32(float f) {
    unsigned u;
    asm("cvt.rna.tf32.f32 %0, %1;" : "=r"(u) : "f"(f));
    return u;
}

__device__ __forceinline__ void mma_tf32(
    float& c0, float& c1, float& c2, float& c3,
    unsigned a0, unsigned a1, unsigned a2, unsigned a3,
    unsigned b0, unsigned b1)
{
    asm volatile(
        "mma.sync.aligned.m16n8k8.row.col.f32.tf32.tf32.f32 "
        "{%0,%1,%2,%3}, {%4,%5,%6,%7}, {%8,%9}, {%0,%1,%2,%3};\n"
        : "+f"(c0), "+f"(c1), "+f"(c2), "+f"(c3)
        : "r"(a0), "r"(a1), "r"(a2), "r"(a3), "r"(b0), "r"(b1));
}

// ---------------- RoPE table (double precision, tiny) -----------------------
__global__ void rope_table_kernel() {
    int idx = blockIdx.x * blockDim.x + threadIdx.x;
    if (idx >= L_ * 32) return;
    int l = idx >> 5, j = idx & 31;
    double invf = exp(-((double)(2 * j) / 64.0) * log(10000.0));
    double a = (double)l * invf;
    g_cos[idx] = (float)cos(a);
    g_sin[idx] = (float)sin(a);
}

// ---------------- tf32 tensor-core GEMM ------------------------------------
// BM=128, BN=64, BK=32; 256 threads = 8 warps (4 m-warps x 2 n-warps),
// warp tile 32x32 via m16n8k8: 2 m-frags x 4 n-frags x 4 k-steps.
// MODE 0: A = plain row-major [M,1024] (projections, blockIdx.z selects W)
// MODE 1: A = g_Oh gathered from [B,H,L,DH] layout (output projection)
template<int MODE>
__global__ __launch_bounds__(256) void gemm_tf32_kernel(
    const float* __restrict__ Aq, const float* __restrict__ Ak, const float* __restrict__ Av,
    const float* __restrict__ W0, const float* __restrict__ b0p,
    const float* __restrict__ W1, const float* __restrict__ b1p,
    const float* __restrict__ W2, const float* __restrict__ b2p,
    const float* __restrict__ W3, const float* __restrict__ b3p,
    float* __restrict__ out_override)
{
    __shared__ float As[128][36];   // stride 36: conflict-free frag loads
    __shared__ float Bs[32][72];    // stride 72: conflict-free frag loads

    int n0 = blockIdx.x * 64;
    int m0 = blockIdx.y * 128;

    const float* A;
    const float* W;
    const float* bias;
    float* out;
    if (MODE == 0) {
        int wsel = blockIdx.z;
        A    = (wsel == 1) ? Ak : (wsel == 2) ? Av : Aq;   // U uses query
        W    = (wsel == 0) ? W0 : (wsel == 1) ? W1 : (wsel == 2) ? W2 : W3;
        bias = (wsel == 0) ? b0p : (wsel == 1) ? b1p : (wsel == 2) ? b2p : b3p;
        out  = g_P[wsel];
    } else {
        A = nullptr; W = W0; bias = b0p; out = out_override;
    }

    int tid = threadIdx.x;
    int w = tid >> 5, lane = tid & 31;
    int wm = w & 3, wn = w >> 2;
    int grp = lane >> 2, tig = lane & 3;

    float acc[2][4][4];
#pragma unroll
    for (int mt = 0; mt < 2; mt++)
#pragma unroll
        for (int nt = 0; nt < 4; nt++)
#pragma unroll
            for (int r = 0; r < 4; r++) acc[mt][nt][r] = 0.f;

    for (int kt = 0; kt < D_; kt += 32) {
        // fill A tile 128x32
#pragma unroll
        for (int u = 0; u < 4; u++) {
            int idx = tid + u * 256;
            int r = idx >> 3, k4 = (idx & 7) * 4;
            float4 v;
            if (MODE == 0) {
                v = *(const float4*)&A[(size_t)(m0 + r) * D_ + kt + k4];
            } else {
                int m = m0 + r;
                int bI = m >> 11, lI = m & 2047;
                int k = kt + k4;
                int hI = k >> 6, dhI = k & 63;
                v = *(const float4*)&g_Oh[(((size_t)bI * H_ + hI) * L_ + lI) * DH_ + dhI];
            }
            *(float4*)&As[r][k4] = v;
        }
        // fill B tile 32x64
#pragma unroll
        for (int u = 0; u < 2; u++) {
            int idx = tid + u * 256;
            int r = idx >> 4, n4 = (idx & 15) * 4;
            float4 v = *(const float4*)&W[(size_t)(kt + r) * D_ + n0 + n4];
            *(float4*)&Bs[r][n4] = v;
        }
        __syncthreads();

#pragma unroll
        for (int ks = 0; ks < 4; ks++) {
            int kb = ks * 8;
            unsigned af[2][4], bf[4][2];
#pragma unroll
            for (int mt = 0; mt < 2; mt++) {
                int row = wm * 32 + mt * 16 + grp;
                af[mt][0] = f2tf32(As[row][kb + tig]);
                af[mt][1] = f2tf32(As[row + 8][kb + tig]);
                af[mt][2] = f2tf32(As[row][kb + tig + 4]);
                af[mt][3] = f2tf32(As[row + 8][kb + tig + 4]);
            }
#pragma unroll
            for (int nt = 0; nt < 4; nt++) {
                int col = wn * 32 + nt * 8 + grp;
                bf[nt][0] = f2tf32(Bs[kb + tig][col]);
                bf[nt][1] = f2tf32(Bs[kb + tig + 4][col]);
            }
#pragma unroll
            for (int mt = 0; mt < 2; mt++)
#pragma unroll
                for (int nt = 0; nt < 4; nt++)
                    mma_tf32(acc[mt][nt][0], acc[mt][nt][1], acc[mt][nt][2], acc[mt][nt][3],
                             af[mt][0], af[mt][1], af[mt][2], af[mt][3],
                             bf[nt][0], bf[nt][1]);
        }
        __syncthreads();
    }

#pragma unroll
    for (int mt = 0; mt < 2; mt++) {
        int row = m0 + wm * 32 + mt * 16 + grp;
#pragma unroll
        for (int nt = 0; nt < 4; nt++) {
            int col = n0 + wn * 32 + nt * 8 + tig * 2;
            out[(size_t)row * D_ + col]           = acc[mt][nt][0] + bias[col];
            out[(size_t)row * D_ + col + 1]       = acc[mt][nt][1] + bias[col + 1];
            out[(size_t)(row + 8) * D_ + col]     = acc[mt][nt][2] + bias[col];
            out[(size_t)(row + 8) * D_ + col + 1] = acc[mt][nt][3] + bias[col + 1];
        }
    }
}

// ---------------- elementwise prep: RoPE, gating, head layout ---------------
__global__ __launch_bounds__(256) void prep_kernel(
    const int* __restrict__ action_ids,
    const float* __restrict__ action_emb,
    const float* __restrict__ Wap,
    const float* __restrict__ bap)
{
    int idx = blockIdx.x * blockDim.x + threadIdx.x;
    if (idx >= M_ * D_) return;
    int m = idx / D_, d = idx % D_;
    int b = m / L_, l = m % L_;
    int h = d >> 6, dh = d & 63;

    float q  = g_P[0][(size_t)idx];
    float kk = g_P[1][(size_t)idx];
    float v  = g_P[2][(size_t)idx];
    float u  = g_P[3][(size_t)idx];

    int aid = action_ids[m];
    float g = bap[d];
    const float* ae = action_emb + aid * 16;
#pragma unroll
    for (int j = 0; j < 16; j++) g = fmaf(ae[j], Wap[j * D_ + d], g);
    float gate = 1.f / (1.f + __expf(-(u + g)));

    int partner = (dh < 32) ? (dh + 32) : (dh - 32);
    float sgn = (dh < 32) ? -1.f : 1.f;
    size_t pidx = (size_t)m * D_ + h * 64 + partner;
    float qr = sgn * g_P[0][pidx];
    float kr = sgn * g_P[1][pidx];

    int ji = dh >> 1;
    float c = g_cos[l * 32 + ji], s = g_sin[l * 32 + ji];

    size_t oidx = ((size_t)(b * H_ + h) * L_ + l) * DH_ + dh;
    g_Qh[oidx] = (q * c + qr * s) * 0.125f;   // pre-scale by DH^-0.5
    g_Kh[oidx] = kk * c + kr * s;
    g_Vh[oidx] = v * gate;
}

// ---------------- flash attention (fp32, online softmax) -------------------
// grid: (L/64 query tiles, B*H); 256 threads; dynamic smem ~72KB
// Q,K stored transposed [dh][q] so score-loop operands are single float4 LDS.
__global__ __launch_bounds__(256) void attn_kernel(
    const unsigned char* __restrict__ maskb,
    const int* __restrict__ td,
    const float* __restrict__ td_emb,
    const float* __restrict__ td_gate)
{
    extern __shared__ float sm[];
    float* Qt = sm;                    // [64 dh][68 q]
    float* Kt = sm + 64 * 68;          // [64 dh][68 k]
    float* Vs = sm + 2 * 64 * 68;      // [64 k][68 dh]
    float* Ps = sm + 3 * 64 * 68;      // [64 q][65 k]
    float* biask = Ps + 64 * 65;       // [64]
    unsigned char* Ms = (unsigned char*)(biask + 64); // [64][64]

    int tid = threadIdx.x;
    int tys = tid >> 4, txs = tid & 15;
    int q0 = blockIdx.x * 64;
    int bh = blockIdx.y;
    int b = bh >> 4, h = bh & 15;

    const float* Qbase = g_Qh + ((size_t)bh * L_) * DH_;
    const float* Kbase = g_Kh + ((size_t)bh * L_) * DH_;
    const float* Vbase = g_Vh + ((size_t)bh * L_) * DH_;

    // Q fill (transposed): lanes span 32 consecutive rows -> conflict-free STS
#pragma unroll
    for (int i = 0; i < 4; i++) {
        int fid = tid + i * 256;
        int r = fid & 63, c4 = (fid >> 6) * 4;
        float4 v = *(const float4*)&Qbase[(size_t)(q0 + r) * DH_ + c4];
        Qt[(c4 + 0) * 68 + r] = v.x;
        Qt[(c4 + 1) * 68 + r] = v.y;
        Qt[(c4 + 2) * 68 + r] = v.z;
        Qt[(c4 + 3) * 68 + r] = v.w;
    }

    int mwid = (maskb[0] != 0 && maskb[1] != 0) ? 1 : 4;
    float sg = 1.f / (1.f + __expf(-td_gate[0]));

    float o[4][4], m_run[4], l_run[4];
#pragma unroll
    for (int i = 0; i < 4; i++) {
        m_run[i] = -INFINITY; l_run[i] = 0.f;
#pragma unroll
        for (int j = 0; j < 4; j++) o[i][j] = 0.f;
    }

    for (int t = 0; t < L_ / 64; t++) {
        int k0 = t * 64;
        __syncthreads();  // previous tile fully consumed
#pragma unroll
        for (int i = 0; i < 4; i++) {
            int fid = tid + i * 256;
            int r = fid & 63, c4 = (fid >> 6) * 4;
            float4 kv = *(const float4*)&Kbase[(size_t)(k0 + r) * DH_ + c4];
            Kt[(c4 + 0) * 68 + r] = kv.x;
            Kt[(c4 + 1) * 68 + r] = kv.y;
            Kt[(c4 + 2) * 68 + r] = kv.z;
            Kt[(c4 + 3) * 68 + r] = kv.w;
            float4 vv = *(const float4*)&Vbase[(size_t)(k0 + r) * DH_ + c4];
            *(float4*)&Vs[r * 68 + c4] = vv;
        }
        if (tid < 64) {
            int tv = td[b * L_ + k0 + tid];
            tv = min(max(tv, 0), 127);
            biask[tid] = sg * td_emb[tv * H_ + h];
        }
        if (mwid == 1) {
#pragma unroll
            for (int i = 0; i < 16; i++) {
                int idx = tid + i * 256;
                int qq = idx >> 6, kk2 = idx & 63;
                Ms[idx] = maskb[(size_t)(b * L_ + q0 + qq) * L_ + k0 + kk2];
            }
        } else {
            const unsigned int* m32 = (const unsigned int*)maskb;
#pragma unroll
            for (int i = 0; i < 16; i++) {
                int idx = tid + i * 256;
                int qq = idx >> 6, kk2 = idx & 63;
                Ms[idx] = (m32[(size_t)(b * L_ + q0 + qq) * L_ + k0 + kk2] != 0u) ? 1 : 0;
            }
        }
        __syncthreads();

        // scores S = Q . K^T  (Q pre-scaled); both operands one LDS.128/step
        float s[4][4];
#pragma unroll
        for (int i = 0; i < 4; i++)
#pragma unroll
            for (int j = 0; j < 4; j++) s[i][j] = 0.f;
#pragma unroll 8
        for (int dh = 0; dh < 64; dh++) {
            float4 a4 = *(const float4*)&Qt[dh * 68 + tys * 4];
            float4 b4 = *(const float4*)&Kt[dh * 68 + txs * 4];
            float a[4] = {a4.x, a4.y, a4.z, a4.w};
            float bb[4] = {b4.x, b4.y, b4.z, b4.w};
#pragma unroll
            for (int i = 0; i < 4; i++)
#pragma unroll
                for (int j = 0; j < 4; j++) s[i][j] = fmaf(a[i], bb[j], s[i][j]);
        }
#pragma unroll
        for (int i = 0; i < 4; i++)
#pragma unroll
            for (int j = 0; j < 4; j++) {
                int kc = txs * 4 + j;
                float v2 = s[i][j] + biask[kc];
                s[i][j] = Ms[(tys * 4 + i) * 64 + kc] ? v2 : -INFINITY;
            }

        // online softmax update
#pragma unroll
        for (int i = 0; i < 4; i++) {
            float mt = fmaxf(fmaxf(s[i][0], s[i][1]), fmaxf(s[i][2], s[i][3]));
#pragma unroll
            for (int off = 8; off >= 1; off >>= 1)
                mt = fmaxf(mt, __shfl_xor_sync(0xffffffffu, mt, off));
            float mn = fmaxf(m_run[i], mt);
            float sc = (m_run[i] == -INFINITY) ? 0.f : __expf(m_run[i] - mn);
            float mnu = (mn == -INFINITY) ? 0.f : mn;
            float p0 = __expf(s[i][0] - mnu);
            float p1 = __expf(s[i][1] - mnu);
            float p2 = __expf(s[i][2] - mnu);
            float p3 = __expf(s[i][3] - mnu);
            float ls = (p0 + p1) + (p2 + p3);
#pragma unroll
            for (int off = 8; off >= 1; off >>= 1)
                ls += __shfl_xor_sync(0xffffffffu, ls, off);
            l_run[i] = l_run[i] * sc + ls;
            m_run[i] = mn;
            float* pr = &Ps[(tys * 4 + i) * 65 + txs * 4];
            pr[0] = p0; pr[1] = p1; pr[2] = p2; pr[3] = p3;
#pragma unroll
            for (int j = 0; j < 4; j++) o[i][j] *= sc;
        }
        __syncthreads();

        // o += Ps @ Vs   (P broadcast scalars, V one float4)
#pragma unroll 4
        for (int c = 0; c < 64; c++) {
            float a[4];
#pragma unroll
            for (int i = 0; i < 4; i++) a[i] = Ps[(tys * 4 + i) * 65 + c];
            float4 v4 = *(const float4*)&Vs[c * 68 + txs * 4];
            float vv[4] = {v4.x, v4.y, v4.z, v4.w};
#pragma unroll
            for (int i = 0; i < 4; i++)
#pragma unroll
                for (int j = 0; j < 4; j++) o[i][j] = fmaf(a[i], vv[j], o[i][j]);
        }
    }

#pragma unroll
    for (int i = 0; i < 4; i++) {
        float inv = 1.f / l_run[i];
#pragma unroll
        for (int j = 0; j < 4; j++)
            g_Oh[((size_t)bh * L_ + q0 + tys * 4 + i) * DH_ + txs * 4 + j] = o[i][j] * inv;
    }
}

// ---------------- launch ----------------------------------------------------
extern "C" void kernel_launch(void* const* d_in, const int* in_sizes, int n_in,
                              void* d_out, int out_size)
{
    const float* query      = (const float*)d_in[0];
    const float* key        = (const float*)d_in[1];
    const float* value      = (const float*)d_in[2];
    const unsigned char* am = (const unsigned char*)d_in[3];
    const int*   action_ids = (const int*)d_in[4];
    const int*   time_delta = (const int*)d_in[5];
    const float* Wq = (const float*)d_in[6];
    const float* bq = (const float*)d_in[7];
    const float* Wk = (const float*)d_in[8];
    const float* bk = (const float*)d_in[9];
    const float* Wv = (const float*)d_in[10];
    const float* bv = (const float*)d_in[11];
    const float* Wu = (const float*)d_in[12];
    const float* bu = (const float*)d_in[13];
    const float* Wo = (const float*)d_in[14];
    const float* bo = (const float*)d_in[15];
    const float* action_emb = (const float*)d_in[16];
    const float* Wap = (const float*)d_in[17];
    const float* bap = (const float*)d_in[18];
    const float* td_emb  = (const float*)d_in[19];
    const float* td_gate = (const float*)d_in[20];
    float* out = (float*)d_out;

    rope_table_kernel<<<(L_ * 32 + 255) / 256, 256>>>();

    gemm_tf32_kernel<0><<<dim3(16, 32, 4), 256>>>(
        query, key, value, Wq, bq, Wk, bk, Wv, bv, Wu, bu, nullptr);

    prep_kernel<<<(M_ * D_ + 255) / 256, 256>>>(action_ids, action_emb, Wap, bap);

    const int attn_smem = (3 * 64 * 68 + 64 * 65 + 64) * (int)sizeof(float) + 64 * 64;
    cudaFuncSetAttribute(attn_kernel, cudaFuncAttributeMaxDynamicSharedMemorySize, attn_smem);
    attn_kernel<<<dim3(L_ / 64, B_ * H_), 256, attn_smem>>>(am, time_delta, td_emb, td_gate);

    gemm_tf32_kernel<1><<<dim3(16, 32), 256>>>(
        nullptr, nullptr, nullptr, Wo, bo,
        nullptr, nullptr, nullptr, nullptr, nullptr, nullptr, out);
}

// round 3
// speedup vs baseline: 2.0548x; 1.5167x over previous
#include <cuda_runtime.h>
#include <math.h>
#include <stdint.h>

#define B_  2
#define L_  2048
#define D_  1024
#define H_  16
#define DH_ 64
#define M_  (B_*L_)   // 4096

#define QT_ 128   // query tile
#define KT_ 64    // key tile

// ---------------- scratch (static device globals; no runtime allocation) ----
__device__ float g_P[4][(size_t)M_*D_];   // raw projections q,k,v,u
__device__ float g_Qh[(size_t)M_*D_];     // [B,H,L,DH], pre-scaled by DH^-0.5
__device__ float g_Kh[(size_t)M_*D_];
__device__ float g_Vh[(size_t)M_*D_];     // gated V
__device__ float g_Oh[(size_t)M_*D_];     // attention output [B,H,L,DH]
__device__ float g_cos[L_*32];
__device__ float g_sin[L_*32];

// ---------------- helpers ---------------------------------------------------
__device__ __forceinline__ unsigned f2tf32(float f) {
    unsigned u;
    asm("cvt.rna.tf32.f32 %0, %1;" : "=r"(u) : "f"(f));
    return u;
}

__device__ __forceinline__ void mma_tf32(
    float& c0, float& c1, float& c2, float& c3,
    unsigned a0, unsigned a1, unsigned a2, unsigned a3,
    unsigned b0, unsigned b1)
{
    asm volatile(
        "mma.sync.aligned.m16n8k8.row.col.f32.tf32.tf32.f32 "
        "{%0,%1,%2,%3}, {%4,%5,%6,%7}, {%8,%9}, {%0,%1,%2,%3};\n"
        : "+f"(c0), "+f"(c1), "+f"(c2), "+f"(c3)
        : "r"(a0), "r"(a1), "r"(a2), "r"(a3), "r"(b0), "r"(b1));
}

// ---------------- RoPE table (double precision, tiny) -----------------------
__global__ void rope_table_kernel() {
    int idx = blockIdx.x * blockDim.x + threadIdx.x;
    if (idx >= L_ * 32) return;
    int l = idx >> 5, j = idx & 31;
    double invf = exp(-((double)(2 * j) / 64.0) * log(10000.0));
    double a = (double)l * invf;
    g_cos[idx] = (float)cos(a);
    g_sin[idx] = (float)sin(a);
}

// ---------------- tf32 tensor-core GEMM (unchanged from R2) -----------------
template<int MODE>
__global__ __launch_bounds__(256) void gemm_tf32_kernel(
    const float* __restrict__ Aq, const float* __restrict__ Ak, const float* __restrict__ Av,
    const float* __restrict__ W0, const float* __restrict__ b0p,
    const float* __restrict__ W1, const float* __restrict__ b1p,
    const float* __restrict__ W2, const float* __restrict__ b2p,
    const float* __restrict__ W3, const float* __restrict__ b3p,
    float* __restrict__ out_override)
{
    __shared__ float As[128][36];
    __shared__ float Bs[32][72];

    int n0 = blockIdx.x * 64;
    int m0 = blockIdx.y * 128;

    const float* A;
    const float* W;
    const float* bias;
    float* out;
    if (MODE == 0) {
        int wsel = blockIdx.z;
        A    = (wsel == 1) ? Ak : (wsel == 2) ? Av : Aq;   // U uses query
        W    = (wsel == 0) ? W0 : (wsel == 1) ? W1 : (wsel == 2) ? W2 : W3;
        bias = (wsel == 0) ? b0p : (wsel == 1) ? b1p : (wsel == 2) ? b2p : b3p;
        out  = g_P[wsel];
    } else {
        A = nullptr; W = W0; bias = b0p; out = out_override;
    }

    int tid = threadIdx.x;
    int w = tid >> 5, lane = tid & 31;
    int wm = w & 3, wn = w >> 2;
    int grp = lane >> 2, tig = lane & 3;

    float acc[2][4][4];
#pragma unroll
    for (int mt = 0; mt < 2; mt++)
#pragma unroll
        for (int nt = 0; nt < 4; nt++)
#pragma unroll
            for (int r = 0; r < 4; r++) acc[mt][nt][r] = 0.f;

    for (int kt = 0; kt < D_; kt += 32) {
#pragma unroll
        for (int u = 0; u < 4; u++) {
            int idx = tid + u * 256;
            int r = idx >> 3, k4 = (idx & 7) * 4;
            float4 v;
            if (MODE == 0) {
                v = *(const float4*)&A[(size_t)(m0 + r) * D_ + kt + k4];
            } else {
                int m = m0 + r;
                int bI = m >> 11, lI = m & 2047;
                int k = kt + k4;
                int hI = k >> 6, dhI = k & 63;
                v = *(const float4*)&g_Oh[(((size_t)bI * H_ + hI) * L_ + lI) * DH_ + dhI];
            }
            *(float4*)&As[r][k4] = v;
        }
#pragma unroll
        for (int u = 0; u < 2; u++) {
            int idx = tid + u * 256;
            int r = idx >> 4, n4 = (idx & 15) * 4;
            float4 v = *(const float4*)&W[(size_t)(kt + r) * D_ + n0 + n4];
            *(float4*)&Bs[r][n4] = v;
        }
        __syncthreads();

#pragma unroll
        for (int ks = 0; ks < 4; ks++) {
            int kb = ks * 8;
            unsigned af[2][4], bf[4][2];
#pragma unroll
            for (int mt = 0; mt < 2; mt++) {
                int row = wm * 32 + mt * 16 + grp;
                af[mt][0] = f2tf32(As[row][kb + tig]);
                af[mt][1] = f2tf32(As[row + 8][kb + tig]);
                af[mt][2] = f2tf32(As[row][kb + tig + 4]);
                af[mt][3] = f2tf32(As[row + 8][kb + tig + 4]);
            }
#pragma unroll
            for (int nt = 0; nt < 4; nt++) {
                int col = wn * 32 + nt * 8 + grp;
                bf[nt][0] = f2tf32(Bs[kb + tig][col]);
                bf[nt][1] = f2tf32(Bs[kb + tig + 4][col]);
            }
#pragma unroll
            for (int mt = 0; mt < 2; mt++)
#pragma unroll
                for (int nt = 0; nt < 4; nt++)
                    mma_tf32(acc[mt][nt][0], acc[mt][nt][1], acc[mt][nt][2], acc[mt][nt][3],
                             af[mt][0], af[mt][1], af[mt][2], af[mt][3],
                             bf[nt][0], bf[nt][1]);
        }
        __syncthreads();
    }

#pragma unroll
    for (int mt = 0; mt < 2; mt++) {
        int row = m0 + wm * 32 + mt * 16 + grp;
#pragma unroll
        for (int nt = 0; nt < 4; nt++) {
            int col = n0 + wn * 32 + nt * 8 + tig * 2;
            out[(size_t)row * D_ + col]           = acc[mt][nt][0] + bias[col];
            out[(size_t)row * D_ + col + 1]       = acc[mt][nt][1] + bias[col + 1];
            out[(size_t)(row + 8) * D_ + col]     = acc[mt][nt][2] + bias[col];
            out[(size_t)(row + 8) * D_ + col + 1] = acc[mt][nt][3] + bias[col + 1];
        }
    }
}

// ---------------- elementwise prep: RoPE, gating, head layout ---------------
__global__ __launch_bounds__(256) void prep_kernel(
    const int* __restrict__ action_ids,
    const float* __restrict__ action_emb,
    const float* __restrict__ Wap,
    const float* __restrict__ bap)
{
    int idx = blockIdx.x * blockDim.x + threadIdx.x;
    if (idx >= M_ * D_) return;
    int m = idx / D_, d = idx % D_;
    int b = m / L_, l = m % L_;
    int h = d >> 6, dh = d & 63;

    float q  = g_P[0][(size_t)idx];
    float kk = g_P[1][(size_t)idx];
    float v  = g_P[2][(size_t)idx];
    float u  = g_P[3][(size_t)idx];

    int aid = action_ids[m];
    float g = bap[d];
    const float* ae = action_emb + aid * 16;
#pragma unroll
    for (int j = 0; j < 16; j++) g = fmaf(ae[j], Wap[j * D_ + d], g);
    float gate = 1.f / (1.f + __expf(-(u + g)));

    int partner = (dh < 32) ? (dh + 32) : (dh - 32);
    float sgn = (dh < 32) ? -1.f : 1.f;
    size_t pidx = (size_t)m * D_ + h * 64 + partner;
    float qr = sgn * g_P[0][pidx];
    float kr = sgn * g_P[1][pidx];

    int ji = dh >> 1;
    float c = g_cos[l * 32 + ji], s = g_sin[l * 32 + ji];

    size_t oidx = ((size_t)(b * H_ + h) * L_ + l) * DH_ + dh;
    g_Qh[oidx] = (q * c + qr * s) * 0.125f;   // pre-scale by DH^-0.5
    g_Kh[oidx] = kk * c + kr * s;
    g_Vh[oidx] = v * gate;
}

// ---------------- tensor-core flash attention (tf32 mma) --------------------
// grid: (L/128 q-tiles, B*H); 256 threads = 8 warps; warp owns 16 q-rows.
// smem floats: Qs[128][68] | Ks[64][68] | Vt[64][68] | Ps[128][68] | bias[64] | Ms bytes
#define QS_OFF 0
#define KS_OFF (128*68)
#define VT_OFF (KS_OFF + 64*68)
#define PS_OFF (VT_OFF + 64*68)
#define BK_OFF (PS_OFF + 128*68)
#define MS_OFF (BK_OFF + 64)              // uint words, 128*16 = 2048 words
#define ATTN_SMEM_FLOATS (MS_OFF + 2048)

__global__ __launch_bounds__(256) void attn_kernel(
    const unsigned char* __restrict__ maskb,
    const int* __restrict__ td,
    const float* __restrict__ td_emb,
    const float* __restrict__ td_gate)
{
    extern __shared__ float sm[];
    float* Qs = sm + QS_OFF;
    float* Ks = sm + KS_OFF;
    float* Vt = sm + VT_OFF;
    float* Ps = sm + PS_OFF;
    float* biask = sm + BK_OFF;
    unsigned* Msw = (unsigned*)(sm + MS_OFF);
    unsigned char* Ms = (unsigned char*)Msw;

    int tid = threadIdx.x;
    int w = tid >> 5, lane = tid & 31;
    int grp = lane >> 2, tig = lane & 3;
    int q0 = blockIdx.x * QT_;
    int bh = blockIdx.y;
    int b = bh >> 4, h = bh & 15;
    int w16 = w * 16;

    const float* Qbase = g_Qh + ((size_t)bh * L_) * DH_;
    const float* Kbase = g_Kh + ((size_t)bh * L_) * DH_;
    const float* Vbase = g_Vh + ((size_t)bh * L_) * DH_;

    // ---- Q fill (natural [q][dh], coalesced) ----
#pragma unroll
    for (int u = 0; u < 8; u++) {
        int fid = tid + u * 256;
        int r = fid >> 4, c4 = (fid & 15) * 4;
        float4 v = *(const float4*)&Qbase[(size_t)(q0 + r) * DH_ + c4];
        *(float4*)&Qs[r * 68 + c4] = v;
    }
    __syncthreads();

    // ---- hoist Q fragments (constant across K tiles) ----
    unsigned af[8][4];
#pragma unroll
    for (int kc = 0; kc < 8; kc++) {
        af[kc][0] = f2tf32(Qs[(w16 + grp) * 68 + kc * 8 + tig]);
        af[kc][1] = f2tf32(Qs[(w16 + grp + 8) * 68 + kc * 8 + tig]);
        af[kc][2] = f2tf32(Qs[(w16 + grp) * 68 + kc * 8 + tig + 4]);
        af[kc][3] = f2tf32(Qs[(w16 + grp + 8) * 68 + kc * 8 + tig + 4]);
    }

    int mwid = (maskb[0] != 0 && maskb[1] != 0) ? 1 : 4;
    float sg = 1.f / (1.f + __expf(-td_gate[0]));

    float o[8][4];
#pragma unroll
    for (int nf = 0; nf < 8; nf++)
#pragma unroll
        for (int r = 0; r < 4; r++) o[nf][r] = 0.f;
    float m0r = -INFINITY, m1r = -INFINITY, l0r = 0.f, l1r = 0.f;

    for (int t = 0; t < L_ / KT_; t++) {
        int k0 = t * KT_;
        __syncthreads();   // previous tile fully consumed

        // K fill: natural [key][dh]
#pragma unroll
        for (int u = 0; u < 4; u++) {
            int fid = tid + u * 256;
            int r = fid >> 4, c4 = (fid & 15) * 4;
            float4 v = *(const float4*)&Kbase[(size_t)(k0 + r) * DH_ + c4];
            *(float4*)&Ks[r * 68 + c4] = v;
        }
        // V fill transposed: Vt[dh][key]; mapping keeps STS conflict-free
#pragma unroll
        for (int u = 0; u < 4; u++) {
            int fid = tid + u * 256;
            int r = fid & 63, c4 = (fid >> 6) * 4;
            float4 v = *(const float4*)&Vbase[(size_t)(k0 + r) * DH_ + c4];
            Vt[(c4 + 0) * 68 + r] = v.x;
            Vt[(c4 + 1) * 68 + r] = v.y;
            Vt[(c4 + 2) * 68 + r] = v.z;
            Vt[(c4 + 3) * 68 + r] = v.w;
        }
        if (tid < 64) {
            int tv = td[b * L_ + k0 + tid];
            tv = min(max(tv, 0), 127);
            biask[tid] = sg * td_emb[tv * H_ + h];
        }
        // mask tile: 128 q rows x 64 k cols as bytes
        if (mwid == 1) {
#pragma unroll
            for (int u = 0; u < 8; u++) {
                int fid = tid + u * 256;
                int qq = fid >> 4, kk4 = (fid & 15) * 4;
                Msw[fid] = *(const unsigned*)&maskb[(size_t)(b * L_ + q0 + qq) * L_ + k0 + kk4];
            }
        } else {
            const unsigned* m32 = (const unsigned*)maskb;
#pragma unroll
            for (int u = 0; u < 8; u++) {
                int fid = tid + u * 256;
                int qq = fid >> 4, kk4 = (fid & 15) * 4;
                const unsigned* src = &m32[(size_t)(b * L_ + q0 + qq) * L_ + k0 + kk4];
                uint4 v = *(const uint4*)src;
                unsigned packed = (v.x ? 1u : 0u) | (v.y ? 0x100u : 0u)
                                | (v.z ? 0x10000u : 0u) | (v.w ? 0x1000000u : 0u);
                Msw[fid] = packed;
            }
        }
        __syncthreads();

        // ---- scores: S(16x64) = Q . K^T via mma ----
        float s[8][4];
#pragma unroll
        for (int nf = 0; nf < 8; nf++) {
            s[nf][0] = 0.f; s[nf][1] = 0.f; s[nf][2] = 0.f; s[nf][3] = 0.f;
#pragma unroll
            for (int kc = 0; kc < 8; kc++) {
                unsigned b0 = f2tf32(Ks[(nf * 8 + grp) * 68 + kc * 8 + tig]);
                unsigned b1 = f2tf32(Ks[(nf * 8 + grp) * 68 + kc * 8 + tig + 4]);
                mma_tf32(s[nf][0], s[nf][1], s[nf][2], s[nf][3],
                         af[kc][0], af[kc][1], af[kc][2], af[kc][3], b0, b1);
            }
        }

        // ---- bias + mask + row max ----
        float mt0 = -INFINITY, mt1 = -INFINITY;
#pragma unroll
        for (int nf = 0; nf < 8; nf++) {
            int c0c = nf * 8 + tig * 2, c1c = c0c + 1;
            float bb0 = biask[c0c], bb1 = biask[c1c];
            int r0 = w16 + grp, r1 = r0 + 8;
            s[nf][0] = Ms[r0 * 64 + c0c] ? (s[nf][0] + bb0) : -INFINITY;
            s[nf][1] = Ms[r0 * 64 + c1c] ? (s[nf][1] + bb1) : -INFINITY;
            s[nf][2] = Ms[r1 * 64 + c0c] ? (s[nf][2] + bb0) : -INFINITY;
            s[nf][3] = Ms[r1 * 64 + c1c] ? (s[nf][3] + bb1) : -INFINITY;
            mt0 = fmaxf(mt0, fmaxf(s[nf][0], s[nf][1]));
            mt1 = fmaxf(mt1, fmaxf(s[nf][2], s[nf][3]));
        }
        mt0 = fmaxf(mt0, __shfl_xor_sync(0xffffffffu, mt0, 1));
        mt0 = fmaxf(mt0, __shfl_xor_sync(0xffffffffu, mt0, 2));
        mt1 = fmaxf(mt1, __shfl_xor_sync(0xffffffffu, mt1, 1));
        mt1 = fmaxf(mt1, __shfl_xor_sync(0xffffffffu, mt1, 2));

        float mn0 = fmaxf(m0r, mt0), mn1 = fmaxf(m1r, mt1);
        float sc0 = (m0r == -INFINITY) ? 0.f : __expf(m0r - mn0);
        float sc1 = (m1r == -INFINITY) ? 0.f : __expf(m1r - mn1);
        float mnu0 = (mn0 == -INFINITY) ? 0.f : mn0;
        float mnu1 = (mn1 == -INFINITY) ? 0.f : mn1;

        // ---- exp, store P to warp-private smem, partial row sums ----
        float la0 = 0.f, la1 = 0.f;
#pragma unroll
        for (int nf = 0; nf < 8; nf++) {
            float p0 = __expf(s[nf][0] - mnu0);
            float p1 = __expf(s[nf][1] - mnu0);
            float p2 = __expf(s[nf][2] - mnu1);
            float p3 = __expf(s[nf][3] - mnu1);
            la0 += p0 + p1; la1 += p2 + p3;
            int cc = nf * 8 + tig * 2;
            *(float2*)&Ps[(w16 + grp) * 68 + cc]     = make_float2(p0, p1);
            *(float2*)&Ps[(w16 + grp + 8) * 68 + cc] = make_float2(p2, p3);
        }
        la0 += __shfl_xor_sync(0xffffffffu, la0, 1);
        la0 += __shfl_xor_sync(0xffffffffu, la0, 2);
        la1 += __shfl_xor_sync(0xffffffffu, la1, 1);
        la1 += __shfl_xor_sync(0xffffffffu, la1, 2);

        l0r = l0r * sc0 + la0;  m0r = mn0;
        l1r = l1r * sc1 + la1;  m1r = mn1;
#pragma unroll
        for (int nf = 0; nf < 8; nf++) {
            o[nf][0] *= sc0; o[nf][1] *= sc0;
            o[nf][2] *= sc1; o[nf][3] *= sc1;
        }
        __syncwarp();

        // ---- PV: O += P(16x64) . V(64x64) via mma ----
        unsigned pf[8][4];
#pragma unroll
        for (int kc = 0; kc < 8; kc++) {
            pf[kc][0] = f2tf32(Ps[(w16 + grp) * 68 + kc * 8 + tig]);
            pf[kc][1] = f2tf32(Ps[(w16 + grp + 8) * 68 + kc * 8 + tig]);
            pf[kc][2] = f2tf32(Ps[(w16 + grp) * 68 + kc * 8 + tig + 4]);
            pf[kc][3] = f2tf32(Ps[(w16 + grp + 8) * 68 + kc * 8 + tig + 4]);
        }
#pragma unroll
        for (int nf = 0; nf < 8; nf++) {
#pragma unroll
            for (int kc = 0; kc < 8; kc++) {
                unsigned b0 = f2tf32(Vt[(nf * 8 + grp) * 68 + kc * 8 + tig]);
                unsigned b1 = f2tf32(Vt[(nf * 8 + grp) * 68 + kc * 8 + tig + 4]);
                mma_tf32(o[nf][0], o[nf][1], o[nf][2], o[nf][3],
                         pf[kc][0], pf[kc][1], pf[kc][2], pf[kc][3], b0, b1);
            }
        }
    }

    // ---- epilogue ----
    float inv0 = 1.f / l0r, inv1 = 1.f / l1r;
    size_t rbase = (size_t)bh * L_ + q0;
#pragma unroll
    for (int nf = 0; nf < 8; nf++) {
        int cc = nf * 8 + tig * 2;
        *(float2*)&g_Oh[(rbase + w16 + grp) * DH_ + cc] =
            make_float2(o[nf][0] * inv0, o[nf][1] * inv0);
        *(float2*)&g_Oh[(rbase + w16 + grp + 8) * DH_ + cc] =
            make_float2(o[nf][2] * inv1, o[nf][3] * inv1);
    }
}

// ---------------- launch ----------------------------------------------------
extern "C" void kernel_launch(void* const* d_in, const int* in_sizes, int n_in,
                              void* d_out, int out_size)
{
    const float* query      = (const float*)d_in[0];
    const float* key        = (const float*)d_in[1];
    const float* value      = (const float*)d_in[2];
    const unsigned char* am = (const unsigned char*)d_in[3];
    const int*   action_ids = (const int*)d_in[4];
    const int*   time_delta = (const int*)d_in[5];
    const float* Wq = (const float*)d_in[6];
    const float* bq = (const float*)d_in[7];
    const float* Wk = (const float*)d_in[8];
    const float* bk = (const float*)d_in[9];
    const float* Wv = (const float*)d_in[10];
    const float* bv = (const float*)d_in[11];
    const float* Wu = (const float*)d_in[12];
    const float* bu = (const float*)d_in[13];
    const float* Wo = (const float*)d_in[14];
    const float* bo = (const float*)d_in[15];
    const float* action_emb = (const float*)d_in[16];
    const float* Wap = (const float*)d_in[17];
    const float* bap = (const float*)d_in[18];
    const float* td_emb  = (const float*)d_in[19];
    const float* td_gate = (const float*)d_in[20];
    float* out = (float*)d_out;

    rope_table_kernel<<<(L_ * 32 + 255) / 256, 256>>>();

    gemm_tf32_kernel<0><<<dim3(16, 32, 4), 256>>>(
        query, key, value, Wq, bq, Wk, bk, Wv, bv, Wu, bu, nullptr);

    prep_kernel<<<(M_ * D_ + 255) / 256, 256>>>(action_ids, action_emb, Wap, bap);

    const int attn_smem = ATTN_SMEM_FLOATS * (int)sizeof(float);
    cudaFuncSetAttribute(attn_kernel, cudaFuncAttributeMaxDynamicSharedMemorySize, attn_smem);
    attn_kernel<<<dim3(L_ / QT_, B_ * H_), 256, attn_smem>>>(am, time_delta, td_emb, td_gate);

    gemm_tf32_kernel<1><<<dim3(16, 32), 256>>>(
        nullptr, nullptr, nullptr, Wo, bo,
        nullptr, nullptr, nullptr, nullptr, nullptr, nullptr, out);
}

// round 4
// speedup vs baseline: 2.4420x; 1.1884x over previous
#include <cuda_runtime.h>
#include <math.h>
#include <stdint.h>

#define B_  2
#define L_  2048
#define D_  1024
#define H_  16
#define DH_ 64
#define M_  (B_*L_)   // 4096

#define QT_ 128   // query tile
#define KT_ 64    // key tile
#define NT_ (L_/KT_)

// ---------------- scratch (static device globals; no runtime allocation) ----
__device__ float g_P[4][(size_t)M_*D_];   // raw projections q,k,v,u
__device__ float g_Qp[(size_t)M_*D_];     // [B,H,L,perm(DH)], tf32-rounded, pre-scaled
__device__ float g_Kp[(size_t)M_*D_];     // [B,H,L,perm(DH)], tf32-rounded
__device__ float g_Vt[(size_t)M_*D_];     // [B,H,DH,L(perm within 64-tiles)], gated, tf32-rounded
__device__ float g_Oh[(size_t)M_*D_];     // attention output [B,H,L,DH]
__device__ float g_cos[L_*32];
__device__ float g_sin[L_*32];
__device__ float g_bias[B_*H_*L_];        // sigmoid(td_gate)*td_emb per (b,h,key)
__device__ unsigned g_mbits[B_*L_*(L_/32)]; // mask bits, 1 bit per (q,k)

// ---------------- helpers ---------------------------------------------------
__device__ __forceinline__ unsigned f2tf32(float f) {
    unsigned u;
    asm("cvt.rna.tf32.f32 %0, %1;" : "=r"(u) : "f"(f));
    return u;
}

__device__ __forceinline__ void mma_tf32(
    float& c0, float& c1, float& c2, float& c3,
    unsigned a0, unsigned a1, unsigned a2, unsigned a3,
    unsigned b0, unsigned b1)
{
    asm volatile(
        "mma.sync.aligned.m16n8k8.row.col.f32.tf32.tf32.f32 "
        "{%0,%1,%2,%3}, {%4,%5,%6,%7}, {%8,%9}, {%0,%1,%2,%3};\n"
        : "+f"(c0), "+f"(c1), "+f"(c2), "+f"(c3)
        : "r"(a0), "r"(a1), "r"(a2), "r"(a3), "r"(b0), "r"(b1));
}

// k-permutation enabling LDS.128 fragment loads: k = kc*8 + tig + 4h
// -> off = tig*8 + kc + h*32  (bijection on 0..63)
__device__ __forceinline__ int permk(int k) {
    int w8 = k & 7;
    return (w8 & 3) * 8 + (k >> 3) + (w8 >> 2) * 32;
}

__device__ __forceinline__ void cpa16(void* dst, const void* src) {
    unsigned d = (unsigned)__cvta_generic_to_shared(dst);
    asm volatile("cp.async.cg.shared.global [%0], [%1], 16;\n" :: "r"(d), "l"(src));
}
__device__ __forceinline__ void cpa8(void* dst, const void* src) {
    unsigned d = (unsigned)__cvta_generic_to_shared(dst);
    asm volatile("cp.async.ca.shared.global [%0], [%1], 8;\n" :: "r"(d), "l"(src));
}
__device__ __forceinline__ void cpa_commit() {
    asm volatile("cp.async.commit_group;\n");
}
template<int N> __device__ __forceinline__ void cpa_wait() {
    asm volatile("cp.async.wait_group %0;\n" :: "n"(N));
}

// ---------------- RoPE table ------------------------------------------------
__global__ void rope_table_kernel() {
    int idx = blockIdx.x * blockDim.x + threadIdx.x;
    if (idx >= L_ * 32) return;
    int l = idx >> 5, j = idx & 31;
    double invf = exp(-((double)(2 * j) / 64.0) * log(10000.0));
    double a = (double)l * invf;
    g_cos[idx] = (float)cos(a);
    g_sin[idx] = (float)sin(a);
}

// ---------------- mask bit-pack + bias precompute ---------------------------
__global__ void pack_mask_kernel(const unsigned char* __restrict__ maskb) {
    int idx = blockIdx.x * blockDim.x + threadIdx.x;
    if (idx >= B_ * L_ * (L_ / 32)) return;
    int kg = idx & 63;
    int q  = (idx >> 6) & (L_ - 1);
    int b  = idx >> 17;
    bool bytes = (maskb[0] != 0 && maskb[1] != 0);
    unsigned bits = 0;
    if (bytes) {
        const unsigned char* row = maskb + ((size_t)b * L_ + q) * L_ + kg * 32;
#pragma unroll
        for (int j = 0; j < 32; j++) bits |= (row[j] ? 1u : 0u) << j;
    } else {
        const unsigned* row = (const unsigned*)maskb + ((size_t)b * L_ + q) * L_ + kg * 32;
#pragma unroll
        for (int j = 0; j < 32; j++) bits |= (row[j] ? 1u : 0u) << j;
    }
    g_mbits[idx] = bits;
}

__global__ void bias_kernel(const int* __restrict__ td,
                            const float* __restrict__ td_emb,
                            const float* __restrict__ td_gate) {
    int idx = blockIdx.x * blockDim.x + threadIdx.x;
    if (idx >= B_ * H_ * L_) return;
    int k = idx & (L_ - 1);
    int h = (idx >> 11) & 15;
    int b = idx >> 15;
    float sg = 1.f / (1.f + __expf(-td_gate[0]));
    int tv = min(max(td[b * L_ + k], 0), 127);
    g_bias[idx] = sg * td_emb[tv * H_ + h];
}

// ---------------- tf32 tensor-core GEMM (unchanged) -------------------------
template<int MODE>
__global__ __launch_bounds__(256) void gemm_tf32_kernel(
    const float* __restrict__ Aq, const float* __restrict__ Ak, const float* __restrict__ Av,
    const float* __restrict__ W0, const float* __restrict__ b0p,
    const float* __restrict__ W1, const float* __restrict__ b1p,
    const float* __restrict__ W2, const float* __restrict__ b2p,
    const float* __restrict__ W3, const float* __restrict__ b3p,
    float* __restrict__ out_override)
{
    __shared__ float As[128][36];
    __shared__ float Bs[32][72];

    int n0 = blockIdx.x * 64;
    int m0 = blockIdx.y * 128;

    const float* A;
    const float* W;
    const float* bias;
    float* out;
    if (MODE == 0) {
        int wsel = blockIdx.z;
        A    = (wsel == 1) ? Ak : (wsel == 2) ? Av : Aq;
        W    = (wsel == 0) ? W0 : (wsel == 1) ? W1 : (wsel == 2) ? W2 : W3;
        bias = (wsel == 0) ? b0p : (wsel == 1) ? b1p : (wsel == 2) ? b2p : b3p;
        out  = g_P[wsel];
    } else {
        A = nullptr; W = W0; bias = b0p; out = out_override;
    }

    int tid = threadIdx.x;
    int w = tid >> 5, lane = tid & 31;
    int wm = w & 3, wn = w >> 2;
    int grp = lane >> 2, tig = lane & 3;

    float acc[2][4][4];
#pragma unroll
    for (int mt = 0; mt < 2; mt++)
#pragma unroll
        for (int nt = 0; nt < 4; nt++)
#pragma unroll
            for (int r = 0; r < 4; r++) acc[mt][nt][r] = 0.f;

    for (int kt = 0; kt < D_; kt += 32) {
#pragma unroll
        for (int u = 0; u < 4; u++) {
            int idx = tid + u * 256;
            int r = idx >> 3, k4 = (idx & 7) * 4;
            float4 v;
            if (MODE == 0) {
                v = *(const float4*)&A[(size_t)(m0 + r) * D_ + kt + k4];
            } else {
                int m = m0 + r;
                int bI = m >> 11, lI = m & 2047;
                int k = kt + k4;
                int hI = k >> 6, dhI = k & 63;
                v = *(const float4*)&g_Oh[(((size_t)bI * H_ + hI) * L_ + lI) * DH_ + dhI];
            }
            *(float4*)&As[r][k4] = v;
        }
#pragma unroll
        for (int u = 0; u < 2; u++) {
            int idx = tid + u * 256;
            int r = idx >> 4, n4 = (idx & 15) * 4;
            float4 v = *(const float4*)&W[(size_t)(kt + r) * D_ + n0 + n4];
            *(float4*)&Bs[r][n4] = v;
        }
        __syncthreads();

#pragma unroll
        for (int ks = 0; ks < 4; ks++) {
            int kb = ks * 8;
            unsigned af[2][4], bf[4][2];
#pragma unroll
            for (int mt = 0; mt < 2; mt++) {
                int row = wm * 32 + mt * 16 + grp;
                af[mt][0] = f2tf32(As[row][kb + tig]);
                af[mt][1] = f2tf32(As[row + 8][kb + tig]);
                af[mt][2] = f2tf32(As[row][kb + tig + 4]);
                af[mt][3] = f2tf32(As[row + 8][kb + tig + 4]);
            }
#pragma unroll
            for (int nt = 0; nt < 4; nt++) {
                int col = wn * 32 + nt * 8 + grp;
                bf[nt][0] = f2tf32(Bs[kb + tig][col]);
                bf[nt][1] = f2tf32(Bs[kb + tig + 4][col]);
            }
#pragma unroll
            for (int mt = 0; mt < 2; mt++)
#pragma unroll
                for (int nt = 0; nt < 4; nt++)
                    mma_tf32(acc[mt][nt][0], acc[mt][nt][1], acc[mt][nt][2], acc[mt][nt][3],
                             af[mt][0], af[mt][1], af[mt][2], af[mt][3],
                             bf[nt][0], bf[nt][1]);
        }
        __syncthreads();
    }

#pragma unroll
    for (int mt = 0; mt < 2; mt++) {
        int row = m0 + wm * 32 + mt * 16 + grp;
#pragma unroll
        for (int nt = 0; nt < 4; nt++) {
            int col = n0 + wn * 32 + nt * 8 + tig * 2;
            out[(size_t)row * D_ + col]           = acc[mt][nt][0] + bias[col];
            out[(size_t)row * D_ + col + 1]       = acc[mt][nt][1] + bias[col + 1];
            out[(size_t)(row + 8) * D_ + col]     = acc[mt][nt][2] + bias[col];
            out[(size_t)(row + 8) * D_ + col + 1] = acc[mt][nt][3] + bias[col + 1];
        }
    }
}

// ---------------- prep: RoPE, gating, head layout + tf32-round + permute ----
__global__ __launch_bounds__(256) void prep_kernel(
    const int* __restrict__ action_ids,
    const float* __restrict__ action_emb,
    const float* __restrict__ Wap,
    const float* __restrict__ bap)
{
    int idx = blockIdx.x * blockDim.x + threadIdx.x;
    if (idx >= M_ * D_) return;
    int m = idx / D_, d = idx % D_;
    int b = m / L_, l = m % L_;
    int h = d >> 6, dh = d & 63;

    float q  = g_P[0][(size_t)idx];
    float kk = g_P[1][(size_t)idx];
    float v  = g_P[2][(size_t)idx];
    float u  = g_P[3][(size_t)idx];

    int aid = action_ids[m];
    float g = bap[d];
    const float* ae = action_emb + aid * 16;
#pragma unroll
    for (int j = 0; j < 16; j++) g = fmaf(ae[j], Wap[j * D_ + d], g);
    float gate = 1.f / (1.f + __expf(-(u + g)));

    int partner = (dh < 32) ? (dh + 32) : (dh - 32);
    float sgn = (dh < 32) ? -1.f : 1.f;
    size_t pidx = (size_t)m * D_ + h * 64 + partner;
    float qr = sgn * g_P[0][pidx];
    float kr = sgn * g_P[1][pidx];

    int ji = dh >> 1;
    float c = g_cos[l * 32 + ji], s = g_sin[l * 32 + ji];

    int bh = b * H_ + h;
    float qv = (q * c + qr * s) * 0.125f;   // DH^-0.5 pre-scale
    float kv = kk * c + kr * s;
    float vv = v * gate;

    // Q,K: [bh][l][perm(dh)], tf32-rounded
    size_t qkbase = ((size_t)bh * L_ + l) * DH_;
    g_Qp[qkbase + permk(dh)] = __uint_as_float(f2tf32(qv));
    g_Kp[qkbase + permk(dh)] = __uint_as_float(f2tf32(kv));
    // V: [bh][dh][tile*64 + perm(l%64)], tf32-rounded
    size_t vbase = ((size_t)bh * DH_ + dh) * L_ + (l & ~63) + permk(l & 63);
    g_Vt[vbase] = __uint_as_float(f2tf32(vv));
}

// ---------------- tensor-core flash attention (pipelined) -------------------
// smem float offsets
#define KS_O 0                       // 2 x 64x68
#define VT_O (2*64*68)               // 8704
#define PS_O (VT_O + 2*64*68)        // 17408
#define BI_O (PS_O + 128*68)         // 26112  (2 x 64 bias floats)
#define MK_O (BI_O + 2*64)           // 26240  (2 x 256 mask uints)
#define SMEMF (MK_O + 2*256)         // 26752 floats = 107008 B

__device__ __forceinline__ void stage_fill(
    float* sm, int s, int tid, int bh, int b, int q0, int k0)
{
    float* KsS = sm + KS_O + s * 64 * 68;
    float* VtS = sm + VT_O + s * 64 * 68;
#pragma unroll
    for (int u = 0; u < 4; u++) {
        int cid = tid + u * 256;
        int row = cid >> 4, seg = (cid & 15) * 4;
        cpa16(&KsS[row * 68 + seg], &g_Kp[((size_t)bh * L_ + k0 + row) * DH_ + seg]);
        cpa16(&VtS[row * 68 + seg], &g_Vt[((size_t)bh * DH_ + row) * L_ + k0 + seg]);
    }
    if (tid < 16)
        cpa16(sm + BI_O + s * 64 + tid * 4, &g_bias[(size_t)bh * L_ + k0 + tid * 4]);
    if (tid < 128) {
        unsigned* mdst = (unsigned*)(sm + MK_O) + s * 256 + tid * 2;
        cpa8(mdst, &g_mbits[((size_t)b * L_ + q0 + tid) * (L_ / 32) + (k0 >> 5)]);
    }
}

__global__ __launch_bounds__(256) void attn_kernel() {
    extern __shared__ float sm[];
    float* Ps = sm + PS_O;

    int tid = threadIdx.x;
    int w = tid >> 5, lane = tid & 31;
    int grp = lane >> 2, tig = lane & 3;
    int q0 = blockIdx.x * QT_;
    int bh = blockIdx.y;
    int b = bh >> 4;
    int w16 = w * 16;

    // ---- Q fragments straight from gmem (pre-rounded, permuted) ----
    unsigned af[8][4];
    {
        float ql0[8], qh0[8], ql1[8], qh1[8];
        const float* q0p = &g_Qp[((size_t)bh * L_ + q0 + w16 + grp) * DH_ + tig * 8];
        const float* q1p = &g_Qp[((size_t)bh * L_ + q0 + w16 + grp + 8) * DH_ + tig * 8];
        *(float4*)&ql0[0] = *(const float4*)q0p;
        *(float4*)&ql0[4] = *(const float4*)(q0p + 4);
        *(float4*)&qh0[0] = *(const float4*)(q0p + 32);
        *(float4*)&qh0[4] = *(const float4*)(q0p + 36);
        *(float4*)&ql1[0] = *(const float4*)q1p;
        *(float4*)&ql1[4] = *(const float4*)(q1p + 4);
        *(float4*)&qh1[0] = *(const float4*)(q1p + 32);
        *(float4*)&qh1[4] = *(const float4*)(q1p + 36);
#pragma unroll
        for (int kc = 0; kc < 8; kc++) {
            af[kc][0] = __float_as_uint(ql0[kc]);
            af[kc][1] = __float_as_uint(ql1[kc]);
            af[kc][2] = __float_as_uint(qh0[kc]);
            af[kc][3] = __float_as_uint(qh1[kc]);
        }
    }

    float o[8][4];
#pragma unroll
    for (int nf = 0; nf < 8; nf++)
#pragma unroll
        for (int r = 0; r < 4; r++) o[nf][r] = 0.f;
    float m0r = -INFINITY, m1r = -INFINITY, l0r = 0.f, l1r = 0.f;

    stage_fill(sm, 0, tid, bh, b, q0, 0);
    cpa_commit();

    for (int t = 0; t < NT_; t++) {
        if (t + 1 < NT_) {
            stage_fill(sm, (t + 1) & 1, tid, bh, b, q0, (t + 1) * KT_);
            cpa_commit();
            cpa_wait<1>();
        } else {
            cpa_wait<0>();
        }
        __syncthreads();

        int s = t & 1;
        float* KsS = sm + KS_O + s * 64 * 68;
        float* VtS = sm + VT_O + s * 64 * 68;
        float* biasS = sm + BI_O + s * 64;
        const unsigned* mk = (const unsigned*)(sm + MK_O) + s * 256;

        unsigned mr0lo = mk[(w16 + grp) * 2],     mr0hi = mk[(w16 + grp) * 2 + 1];
        unsigned mr1lo = mk[(w16 + grp + 8) * 2], mr1hi = mk[(w16 + grp + 8) * 2 + 1];

        // ---- scores ----
        float sc[8][4];
#pragma unroll
        for (int nf = 0; nf < 8; nf++) {
            sc[nf][0] = 0.f; sc[nf][1] = 0.f; sc[nf][2] = 0.f; sc[nf][3] = 0.f;
            const float* kp = &KsS[(nf * 8 + grp) * 68 + tig * 8];
            float kl[8], kh[8];
            *(float4*)&kl[0] = *(const float4*)kp;
            *(float4*)&kl[4] = *(const float4*)(kp + 4);
            *(float4*)&kh[0] = *(const float4*)(kp + 32);
            *(float4*)&kh[4] = *(const float4*)(kp + 36);
#pragma unroll
            for (int kc = 0; kc < 8; kc++)
                mma_tf32(sc[nf][0], sc[nf][1], sc[nf][2], sc[nf][3],
                         af[kc][0], af[kc][1], af[kc][2], af[kc][3],
                         __float_as_uint(kl[kc]), __float_as_uint(kh[kc]));
        }

        // ---- bias + mask + row max ----
        float mt0 = -INFINITY, mt1 = -INFINITY;
#pragma unroll
        for (int nf = 0; nf < 8; nf++) {
            float2 bb = *(const float2*)&biasS[nf * 8 + tig * 2];
            int bp = (nf & 3) * 8 + tig * 2;
            unsigned m0s = ((nf < 4) ? mr0lo : mr0hi) >> bp;
            unsigned m1s = ((nf < 4) ? mr1lo : mr1hi) >> bp;
            sc[nf][0] = (m0s & 1u) ? (sc[nf][0] + bb.x) : -INFINITY;
            sc[nf][1] = (m0s & 2u) ? (sc[nf][1] + bb.y) : -INFINITY;
            sc[nf][2] = (m1s & 1u) ? (sc[nf][2] + bb.x) : -INFINITY;
            sc[nf][3] = (m1s & 2u) ? (sc[nf][3] + bb.y) : -INFINITY;
            mt0 = fmaxf(mt0, fmaxf(sc[nf][0], sc[nf][1]));
            mt1 = fmaxf(mt1, fmaxf(sc[nf][2], sc[nf][3]));
        }
        mt0 = fmaxf(mt0, __shfl_xor_sync(0xffffffffu, mt0, 1));
        mt0 = fmaxf(mt0, __shfl_xor_sync(0xffffffffu, mt0, 2));
        mt1 = fmaxf(mt1, __shfl_xor_sync(0xffffffffu, mt1, 1));
        mt1 = fmaxf(mt1, __shfl_xor_sync(0xffffffffu, mt1, 2));

        float mn0 = fmaxf(m0r, mt0), mn1 = fmaxf(m1r, mt1);
        float s0 = (m0r == -INFINITY) ? 0.f : __expf(m0r - mn0);
        float s1 = (m1r == -INFINITY) ? 0.f : __expf(m1r - mn1);
        float mnu0 = (mn0 == -INFINITY) ? 0.f : mn0;
        float mnu1 = (mn1 == -INFINITY) ? 0.f : mn1;

        // ---- exp (tf32-rounded), store P permuted, partial sums ----
        float la0 = 0.f, la1 = 0.f;
        int pbase = ((tig * 2) & 3) * 8 + ((tig * 2) >> 2) * 32;
        float* pr0 = &Ps[(w16 + grp) * 68 + pbase];
        float* pr1 = &Ps[(w16 + grp + 8) * 68 + pbase];
#pragma unroll
        for (int nf = 0; nf < 8; nf++) {
            float p0 = __uint_as_float(f2tf32(__expf(sc[nf][0] - mnu0)));
            float p1 = __uint_as_float(f2tf32(__expf(sc[nf][1] - mnu0)));
            float p2 = __uint_as_float(f2tf32(__expf(sc[nf][2] - mnu1)));
            float p3 = __uint_as_float(f2tf32(__expf(sc[nf][3] - mnu1)));
            la0 += p0 + p1; la1 += p2 + p3;
            pr0[nf] = p0; pr0[nf + 8] = p1;
            pr1[nf] = p2; pr1[nf + 8] = p3;
        }
        la0 += __shfl_xor_sync(0xffffffffu, la0, 1);
        la0 += __shfl_xor_sync(0xffffffffu, la0, 2);
        la1 += __shfl_xor_sync(0xffffffffu, la1, 1);
        la1 += __shfl_xor_sync(0xffffffffu, la1, 2);

        l0r = l0r * s0 + la0;  m0r = mn0;
        l1r = l1r * s1 + la1;  m1r = mn1;
#pragma unroll
        for (int nf = 0; nf < 8; nf++) {
            o[nf][0] *= s0; o[nf][1] *= s0;
            o[nf][2] *= s1; o[nf][3] *= s1;
        }
        __syncwarp();

        // ---- P fragments (permuted -> LDS.128) ----
        unsigned pf[8][4];
        {
            float pl0[8], ph0[8], pl1[8], ph1[8];
            const float* pp0 = &Ps[(w16 + grp) * 68 + tig * 8];
            const float* pp1 = &Ps[(w16 + grp + 8) * 68 + tig * 8];
            *(float4*)&pl0[0] = *(const float4*)pp0;
            *(float4*)&pl0[4] = *(const float4*)(pp0 + 4);
            *(float4*)&ph0[0] = *(const float4*)(pp0 + 32);
            *(float4*)&ph0[4] = *(const float4*)(pp0 + 36);
            *(float4*)&pl1[0] = *(const float4*)pp1;
            *(float4*)&pl1[4] = *(const float4*)(pp1 + 4);
            *(float4*)&ph1[0] = *(const float4*)(pp1 + 32);
            *(float4*)&ph1[4] = *(const float4*)(pp1 + 36);
#pragma unroll
            for (int kc = 0; kc < 8; kc++) {
                pf[kc][0] = __float_as_uint(pl0[kc]);
                pf[kc][1] = __float_as_uint(pl1[kc]);
                pf[kc][2] = __float_as_uint(ph0[kc]);
                pf[kc][3] = __float_as_uint(ph1[kc]);
            }
        }

        // ---- PV ----
#pragma unroll
        for (int nf = 0; nf < 8; nf++) {
            const float* vp = &VtS[(nf * 8 + grp) * 68 + tig * 8];
            float vl[8], vh[8];
            *(float4*)&vl[0] = *(const float4*)vp;
            *(float4*)&vl[4] = *(const float4*)(vp + 4);
            *(float4*)&vh[0] = *(const float4*)(vp + 32);
            *(float4*)&vh[4] = *(const float4*)(vp + 36);
#pragma unroll
            for (int kc = 0; kc < 8; kc++)
                mma_tf32(o[nf][0], o[nf][1], o[nf][2], o[nf][3],
                         pf[kc][0], pf[kc][1], pf[kc][2], pf[kc][3],
                         __float_as_uint(vl[kc]), __float_as_uint(vh[kc]));
        }
        __syncthreads();
    }

    // ---- epilogue ----
    float inv0 = 1.f / l0r, inv1 = 1.f / l1r;
    size_t rbase = (size_t)bh * L_ + q0;
#pragma unroll
    for (int nf = 0; nf < 8; nf++) {
        int cc = nf * 8 + tig * 2;
        *(float2*)&g_Oh[(rbase + w16 + grp) * DH_ + cc] =
            make_float2(o[nf][0] * inv0, o[nf][1] * inv0);
        *(float2*)&g_Oh[(rbase + w16 + grp + 8) * DH_ + cc] =
            make_float2(o[nf][2] * inv1, o[nf][3] * inv1);
    }
}

// ---------------- launch ----------------------------------------------------
extern "C" void kernel_launch(void* const* d_in, const int* in_sizes, int n_in,
                              void* d_out, int out_size)
{
    const float* query      = (const float*)d_in[0];
    const float* key        = (const float*)d_in[1];
    const float* value      = (const float*)d_in[2];
    const unsigned char* am = (const unsigned char*)d_in[3];
    const int*   action_ids = (const int*)d_in[4];
    const int*   time_delta = (const int*)d_in[5];
    const float* Wq = (const float*)d_in[6];
    const float* bq = (const float*)d_in[7];
    const float* Wk = (const float*)d_in[8];
    const float* bk = (const float*)d_in[9];
    const float* Wv = (const float*)d_in[10];
    const float* bv = (const float*)d_in[11];
    const float* Wu = (const float*)d_in[12];
    const float* bu = (const float*)d_in[13];
    const float* Wo = (const float*)d_in[14];
    const float* bo = (const float*)d_in[15];
    const float* action_emb = (const float*)d_in[16];
    const float* Wap = (const float*)d_in[17];
    const float* bap = (const float*)d_in[18];
    const float* td_emb  = (const float*)d_in[19];
    const float* td_gate = (const float*)d_in[20];
    float* out = (float*)d_out;

    rope_table_kernel<<<(L_ * 32 + 255) / 256, 256>>>();
    pack_mask_kernel<<<(B_ * L_ * (L_ / 32) + 255) / 256, 256>>>(am);
    bias_kernel<<<(B_ * H_ * L_ + 255) / 256, 256>>>(time_delta, td_emb, td_gate);

    gemm_tf32_kernel<0><<<dim3(16, 32, 4), 256>>>(
        query, key, value, Wq, bq, Wk, bk, Wv, bv, Wu, bu, nullptr);

    prep_kernel<<<(M_ * D_ + 255) / 256, 256>>>(action_ids, action_emb, Wap, bap);

    const int attn_smem = SMEMF * (int)sizeof(float);
    cudaFuncSetAttribute(attn_kernel, cudaFuncAttributeMaxDynamicSharedMemorySize, attn_smem);
    attn_kernel<<<dim3(L_ / QT_, B_ * H_), 256, attn_smem>>>();

    gemm_tf32_kernel<1><<<dim3(16, 32), 256>>>(
        nullptr, nullptr, nullptr, Wo, bo,
        nullptr, nullptr, nullptr, nullptr, nullptr, nullptr, out);
}